// round 16
// baseline (speedup 1.0000x reference)
#include <cuda_runtime.h>
#include <math.h>
#include <stdint.h>

// ---------------- problem constants ----------------
#define Bc 4
#define Nc 1500
#define Kc 30
#define Lc 4
#define BNc (Bc*Nc)          // 6000
#define ECNT (BNc*Kc)        // 180000
#define SEG 188              // 8*188 >= 1500

// weight arena layout (floats)
#define OFF_WV 0
#define LAYER_FLOATS 196608
#define ARENA_N (131072 + Lc*LAYER_FLOATS)   // 917504
#define LOFF(l) (131072 + (l)*LAYER_FLOATS)
#define LOFF_WQ  0
#define LOFF_WK  16384
#define LOFF_WVB 32768
#define LOFF_WO  49152
#define LOFF_FF1 65536
#define LOFF_FF2 131072

// ---------------- device scratch ----------------
__device__ int   g_Eidx[ECNT];
__device__ float g_fs[(size_t)ECNT*32];
__device__ float g_ms[ECNT];
__device__ float g_hVa[(size_t)BNc*128];
__device__ float g_hVb[(size_t)BNc*128];
__device__ float g_hVm[(size_t)BNc*128];
__device__ float g_Q[(size_t)BNc*128];
__device__ float g_Kn[(size_t)BNc*128];
__device__ float g_Vn[(size_t)BNc*128];
__device__ float g_att[(size_t)BNc*128];
__device__ float g_ff[(size_t)BNc*512];
__device__ uint32_t g_Whi[ARENA_N];
__device__ uint32_t g_Wlo[ARENA_N];
// precomputed constants
__device__ float g_Wcomb[32*128];
__device__ float g_G[32*32];
__device__ float g_m[32];
__device__ float g_s[128];
__device__ float g_bp[128];
__device__ float g_At[Lc*4*32*32];
__device__ float g_sv[Lc*128];
__device__ float g_bv[Lc*128];
__device__ float g_Wcv[Lc*32*128];
__device__ float g_sv2[Lc*128];
__device__ float g_bv2[Lc*128];

__device__ __forceinline__ float wred(float v) {
    #pragma unroll
    for (int o = 16; o > 0; o >>= 1) v += __shfl_xor_sync(0xffffffffu, v, o);
    return v;
}

__device__ __forceinline__ uint32_t f2tf(float x) {
    uint32_t r; asm("cvt.rna.tf32.f32 %0, %1;" : "=r"(r) : "f"(x)); return r;
}
__device__ __forceinline__ void f2tf2(float x, uint32_t& hi, uint32_t& lo) {
    hi = f2tf(x);
    lo = f2tf(x - __uint_as_float(hi));
}

__device__ __forceinline__ void mma8(float* c, const uint32_t* a, const uint32_t* b) {
    asm volatile("mma.sync.aligned.m16n8k8.row.col.f32.tf32.tf32.f32 "
        "{%0,%1,%2,%3}, {%4,%5,%6,%7}, {%8,%9}, {%0,%1,%2,%3};"
        : "+f"(c[0]), "+f"(c[1]), "+f"(c[2]), "+f"(c[3])
        : "r"(a[0]), "r"(a[1]), "r"(a[2]), "r"(a[3]), "r"(b[0]), "r"(b[1]));
}

#define SMEM_LOOP_BYTES 25600

// ---------------- weight split ----------------
__global__ void split_all_kernel(const float* __restrict__ W_v, const float* __restrict__ Wq,
                                 const float* __restrict__ Wk, const float* __restrict__ Wv_a,
                                 const float* __restrict__ Wo, const float* __restrict__ W_ff1,
                                 const float* __restrict__ W_ff2)
{
    int idx = blockIdx.x * 256 + threadIdx.x;
    if (idx >= ARENA_N) return;
    float v;
    if (idx < 131072) {
        v = W_v[idx];
    } else {
        int r = idx - 131072;
        int l = r / LAYER_FLOATS;
        int q = r - l * LAYER_FLOATS;
        if      (q < LOFF_WK)  v = Wq  [(size_t)l*16384 + q];
        else if (q < LOFF_WVB) v = Wk  [(size_t)l*32768 + 16384 + (q - LOFF_WK)];
        else if (q < LOFF_WO)  v = Wv_a[(size_t)l*32768 + 16384 + (q - LOFF_WVB)];
        else if (q < LOFF_FF1) v = Wo  [(size_t)l*16384 + (q - LOFF_WO)];
        else if (q < LOFF_FF2) v = W_ff1[(size_t)l*65536 + (q - LOFF_FF1)];
        else                   v = W_ff2[(size_t)l*65536 + (q - LOFF_FF2)];
    }
    uint32_t hi, lo;
    f2tf2(v, hi, lo);
    g_Whi[idx] = hi;
    g_Wlo[idx] = lo;
}

// ---------------- 3xTF32 mainloop, register-prefetched, 64x128 tile, 256 threads ----------------
__device__ __forceinline__ void tf32_loop3_pf(const float* __restrict__ A,
    const uint32_t* __restrict__ BHi, const uint32_t* __restrict__ BLo,
    int M, int Nn, int Kk, int Astride, int rowbase, int colbase, char* buf, float acc[2][4][4])
{
    uint32_t (*AsH)[17]  = reinterpret_cast<uint32_t(*)[17]>(buf);
    uint32_t (*AsL)[17]  = reinterpret_cast<uint32_t(*)[17]>(buf + 4352);
    uint32_t (*BsH)[132] = reinterpret_cast<uint32_t(*)[132]>(buf + 8704);
    uint32_t (*BsL)[132] = reinterpret_cast<uint32_t(*)[132]>(buf + 17152);

    int tid = threadIdx.x;
    int warp = tid >> 5, lane = tid & 31;
    int g = lane >> 2, t = lane & 3;
    int warpRow = warp >> 2, warpCol = warp & 3;
    int ar = tid >> 2;
    int ac = (tid & 3) * 4;
    int br = tid >> 5;
    int bc = (tid & 31) * 4;
    bool aval = (rowbase + ar) < M;
    const float* Arow = A + (size_t)(rowbase + ar) * Astride + ac;

    float4 av = aval ? *(const float4*)(Arow) : make_float4(0.f,0.f,0.f,0.f);
    uint4 bh0 = *(const uint4*)(BHi + (size_t)br * Nn + colbase + bc);
    uint4 bl0 = *(const uint4*)(BLo + (size_t)br * Nn + colbase + bc);
    uint4 bh1 = *(const uint4*)(BHi + (size_t)(br + 8) * Nn + colbase + bc);
    uint4 bl1 = *(const uint4*)(BLo + (size_t)(br + 8) * Nn + colbase + bc);
    f2tf2(av.x, AsH[ar][ac+0], AsL[ar][ac+0]);
    f2tf2(av.y, AsH[ar][ac+1], AsL[ar][ac+1]);
    f2tf2(av.z, AsH[ar][ac+2], AsL[ar][ac+2]);
    f2tf2(av.w, AsH[ar][ac+3], AsL[ar][ac+3]);
    *(uint4*)(&BsH[br][bc])     = bh0;
    *(uint4*)(&BsL[br][bc])     = bl0;
    *(uint4*)(&BsH[br + 8][bc]) = bh1;
    *(uint4*)(&BsL[br + 8][bc]) = bl1;
    __syncthreads();

    for (int k0 = 16; ; k0 += 16) {
        bool more = (k0 < Kk);
        if (more) {
            av  = aval ? *(const float4*)(Arow + k0) : make_float4(0.f,0.f,0.f,0.f);
            bh0 = *(const uint4*)(BHi + (size_t)(k0 + br) * Nn + colbase + bc);
            bl0 = *(const uint4*)(BLo + (size_t)(k0 + br) * Nn + colbase + bc);
            bh1 = *(const uint4*)(BHi + (size_t)(k0 + br + 8) * Nn + colbase + bc);
            bl1 = *(const uint4*)(BLo + (size_t)(k0 + br + 8) * Nn + colbase + bc);
        }
        #pragma unroll
        for (int kk = 0; kk < 2; kk++) {
            uint32_t aH[2][4], aL[2][4], bH[4][2], bL[4][2];
            #pragma unroll
            for (int mi = 0; mi < 2; mi++) {
                int rb = warpRow * 32 + mi * 16;
                aH[mi][0] = AsH[rb + g    ][kk*8 + t];
                aH[mi][1] = AsH[rb + g + 8][kk*8 + t];
                aH[mi][2] = AsH[rb + g    ][kk*8 + t + 4];
                aH[mi][3] = AsH[rb + g + 8][kk*8 + t + 4];
                aL[mi][0] = AsL[rb + g    ][kk*8 + t];
                aL[mi][1] = AsL[rb + g + 8][kk*8 + t];
                aL[mi][2] = AsL[rb + g    ][kk*8 + t + 4];
                aL[mi][3] = AsL[rb + g + 8][kk*8 + t + 4];
            }
            #pragma unroll
            for (int ni = 0; ni < 4; ni++) {
                int cb = warpCol * 32 + ni * 8 + g;
                bH[ni][0] = BsH[kk*8 + t    ][cb];
                bH[ni][1] = BsH[kk*8 + t + 4][cb];
                bL[ni][0] = BsL[kk*8 + t    ][cb];
                bL[ni][1] = BsL[kk*8 + t + 4][cb];
            }
            #pragma unroll
            for (int mi = 0; mi < 2; mi++)
                #pragma unroll
                for (int ni = 0; ni < 4; ni++) {
                    mma8(acc[mi][ni], aL[mi], bH[ni]);
                    mma8(acc[mi][ni], aH[mi], bL[ni]);
                    mma8(acc[mi][ni], aH[mi], bH[ni]);
                }
        }
        if (!more) break;
        __syncthreads();
        f2tf2(av.x, AsH[ar][ac+0], AsL[ar][ac+0]);
        f2tf2(av.y, AsH[ar][ac+1], AsL[ar][ac+1]);
        f2tf2(av.z, AsH[ar][ac+2], AsL[ar][ac+2]);
        f2tf2(av.w, AsH[ar][ac+3], AsL[ar][ac+3]);
        *(uint4*)(&BsH[br][bc])     = bh0;
        *(uint4*)(&BsL[br][bc])     = bl0;
        *(uint4*)(&BsH[br + 8][bc]) = bh1;
        *(uint4*)(&BsL[br + 8][bc]) = bl1;
        __syncthreads();
    }
    __syncthreads();
}

// ---------------- epilogue helper ----------------
__device__ __forceinline__ void gemm_store(float acc[2][4][4], const float* bias, float* C,
                                           int M, int Nn, int rowbase, int colbase,
                                           int BIAS, int RELU)
{
    int warp = threadIdx.x >> 5, lane = threadIdx.x & 31;
    int g = lane >> 2, t = lane & 3;
    int warpRow = warp >> 2, warpCol = warp & 3;
    #pragma unroll
    for (int mi = 0; mi < 2; mi++) {
        #pragma unroll
        for (int ni = 0; ni < 4; ni++) {
            int col = colbase + warpCol * 32 + ni * 8 + 2 * t;
            float b0 = BIAS ? bias[col]   : 0.f;
            float b1 = BIAS ? bias[col+1] : 0.f;
            int r0 = rowbase + warpRow * 32 + mi * 16 + g;
            if (r0 < M) {
                float2 o; o.x = acc[mi][ni][0] + b0; o.y = acc[mi][ni][1] + b1;
                if (RELU) { o.x = fmaxf(o.x, 0.f); o.y = fmaxf(o.y, 0.f); }
                *(float2*)(C + (size_t)r0 * Nn + col) = o;
            }
            int r1 = r0 + 8;
            if (r1 < M) {
                float2 o; o.x = acc[mi][ni][2] + b0; o.y = acc[mi][ni][3] + b1;
                if (RELU) { o.x = fmaxf(o.x, 0.f); o.y = fmaxf(o.y, 0.f); }
                *(float2*)(C + (size_t)r1 * Nn + col) = o;
            }
        }
    }
}

// ---------------- tf32x3 GEMM + bias/relu (256 threads) ----------------
template<int BIAS, int RELU>
__global__ void __launch_bounds__(256)
tf32_gemm(const float* __restrict__ A, const uint32_t* __restrict__ BHi, const uint32_t* __restrict__ BLo,
          const float* __restrict__ bias, float* __restrict__ C,
          int M, int Nn, int Kk)
{
    __shared__ __align__(16) char buf[SMEM_LOOP_BYTES];
    float acc[2][4][4];
    #pragma unroll
    for (int mi = 0; mi < 2; mi++)
        #pragma unroll
        for (int ni = 0; ni < 4; ni++)
            #pragma unroll
            for (int q = 0; q < 4; q++) acc[mi][ni][q] = 0.f;

    int rowbase = blockIdx.y * 64, colbase = blockIdx.x * 128;
    tf32_loop3_pf(A, BHi, BLo, M, Nn, Kk, Kk, rowbase, colbase, buf, acc);
    gemm_store(acc, bias, C, M, Nn, rowbase, colbase, BIAS, RELU);
}

// ---------------- 2-way split-K GEMM ----------------
__global__ void __launch_bounds__(256)
tf32_gemm_splitk(const float* __restrict__ A, const uint32_t* __restrict__ BHi, const uint32_t* __restrict__ BLo,
                 float* __restrict__ C0, float* __restrict__ C1, int M, int Kfull)
{
    __shared__ __align__(16) char buf[SMEM_LOOP_BYTES];
    float acc[2][4][4];
    #pragma unroll
    for (int mi = 0; mi < 2; mi++)
        #pragma unroll
        for (int ni = 0; ni < 4; ni++)
            #pragma unroll
            for (int q = 0; q < 4; q++) acc[mi][ni][q] = 0.f;

    int half = Kfull >> 1;
    int koff = blockIdx.x * half;
    float* C = (blockIdx.x == 0) ? C0 : C1;
    int rowbase = blockIdx.y * 64;
    tf32_loop3_pf(A + koff, BHi + (size_t)koff * 128, BLo + (size_t)koff * 128,
                  M, 128, half, Kfull, rowbase, 0, buf, acc);
    gemm_store(acc, nullptr, C, M, 128, rowbase, 0, 0, 0);
}

// ---------------- 4-way split-K GEMM ----------------
__global__ void __launch_bounds__(256)
tf32_gemm_splitk4(const float* __restrict__ A, const uint32_t* __restrict__ BHi, const uint32_t* __restrict__ BLo,
                  float* __restrict__ C0, float* __restrict__ C1,
                  float* __restrict__ C2, float* __restrict__ C3, int M, int Kfull)
{
    __shared__ __align__(16) char buf[SMEM_LOOP_BYTES];
    float acc[2][4][4];
    #pragma unroll
    for (int mi = 0; mi < 2; mi++)
        #pragma unroll
        for (int ni = 0; ni < 4; ni++)
            #pragma unroll
            for (int q = 0; q < 4; q++) acc[mi][ni][q] = 0.f;

    int quarter = Kfull >> 2;
    int koff = blockIdx.x * quarter;
    float* C = (blockIdx.x == 0) ? C0 : (blockIdx.x == 1) ? C1 : (blockIdx.x == 2) ? C2 : C3;
    int rowbase = blockIdx.y * 64;
    tf32_loop3_pf(A + koff, BHi + (size_t)koff * 128, BLo + (size_t)koff * 128,
                  M, 128, quarter, Kfull, rowbase, 0, buf, acc);
    gemm_store(acc, nullptr, C, M, 128, rowbase, 0, 0, 0);
}

// ---------------- tf32x3 qkv GEMM ----------------
__global__ void __launch_bounds__(256)
tf32_gemm_qkv(const float* __restrict__ A, int off0, int off1, int off2,
              float* __restrict__ C0, float* __restrict__ C1, float* __restrict__ C2, int M)
{
    __shared__ __align__(16) char buf[SMEM_LOOP_BYTES];
    int off = (blockIdx.x == 0) ? off0 : (blockIdx.x == 1) ? off1 : off2;
    const uint32_t* BHi = g_Whi + off;
    const uint32_t* BLo = g_Wlo + off;
    float* C = (blockIdx.x == 0) ? C0 : (blockIdx.x == 1) ? C1 : C2;
    float acc[2][4][4];
    #pragma unroll
    for (int mi = 0; mi < 2; mi++)
        #pragma unroll
        for (int ni = 0; ni < 4; ni++)
            #pragma unroll
            for (int q = 0; q < 4; q++) acc[mi][ni][q] = 0.f;

    int rowbase = blockIdx.y * 64;
    tf32_loop3_pf(A, BHi, BLo, M, 128, 128, 128, rowbase, 0, buf, acc);
    gemm_store(acc, nullptr, C, M, 128, rowbase, 0, 0, 0);
}

// ---------------- split-K epilogue: out = p0+p1+p2+p3+bias ----------------
__global__ void sum4_bias_kernel(const float* __restrict__ p0, const float* __restrict__ p1,
                                 const float* __restrict__ p2, const float* __restrict__ p3,
                                 const float* __restrict__ bias, float* __restrict__ out)
{
    int t = blockIdx.x * 256 + threadIdx.x;
    if (t >= BNc * 128) return;
    out[t] = p0[t] + p1[t] + p2[t] + p3[t] + bias[t & 127];
}

// ---------------- split-K epilogue: out = (mask)*LN(p0+p1+(bias)+res) ----------------
template<int BIAS, int MASK>
__global__ void sum2_ln_kernel(const float* __restrict__ p0, const float* __restrict__ p1,
                               const float* __restrict__ bias, const float* __restrict__ res,
                               const float* __restrict__ gamma, const float* __restrict__ beta,
                               const float* __restrict__ mask, float* __restrict__ out)
{
    int row = blockIdx.x;
    int c = threadIdx.x;  // 128
    size_t idx = (size_t)row * 128 + c;
    float v = p0[idx] + p1[idx] + res[idx];
    if (BIAS) v += bias[c];
    float s = v, s2 = v * v;
    #pragma unroll
    for (int o = 16; o > 0; o >>= 1) {
        s  += __shfl_xor_sync(0xffffffffu, s,  o);
        s2 += __shfl_xor_sync(0xffffffffu, s2, o);
    }
    __shared__ float ws[4], ws2[4];
    int w = c >> 5;
    if ((c & 31) == 0) { ws[w] = s; ws2[w] = s2; }
    __syncthreads();
    s  = ws[0] + ws[1] + ws[2] + ws[3];
    s2 = ws2[0] + ws2[1] + ws2[2] + ws2[3];
    float mu = s * (1.f / 128.f);
    float var = s2 * (1.f / 128.f) - mu * mu;
    float y = gamma[c] * (v - mu) * rsqrtf(var + 1e-6f) + beta[c];
    if (MASK) y *= mask[row];
    out[idx] = y;
}

// ---------------- fused top-K + edge features ----------------
// Phase 1: segmented-rescan top-K selection (as before), selections kept in smem.
// Phase 2: each warp computes edge features (fs, ms) for its subset of the 30
//          edges, with the 32x32 G matrix held in per-lane registers (column c).
__global__ void __launch_bounds__(256)
topk_edge_kernel(const float* __restrict__ X, const float* __restrict__ mask,
                 int* __restrict__ Eidx, float* __restrict__ fs, float* __restrict__ ms)
{
    __shared__ float sD[Nc];
    __shared__ float wmin[8];
    __shared__ int   widx[8];
    __shared__ float red8[8];
    __shared__ float s_rowmax;
    __shared__ int   s_win;
    __shared__ int   sSel[Kc];
    __shared__ float sSelD[Kc];
    int row = blockIdx.x;
    int b = row / Nc;
    int i = row - b * Nc;
    int tid = threadIdx.x;
    int warp = tid >> 5, lane = tid & 31;
    const float* Xb = X + (size_t)b * Nc * 3;
    const float* mb = mask + (size_t)b * Nc;

    // G column for this lane, loaded once (coalesced); m[lane] scalar
    float Greg[32];
    #pragma unroll
    for (int j = 0; j < 32; j++) Greg[j] = g_G[j*32 + lane];
    float mlane = g_m[lane];

    float xi0 = Xb[i*3+0], xi1 = Xb[i*3+1], xi2 = Xb[i*3+2];
    float mi = mb[i];
    float lmax = 0.f;
    for (int j = tid; j < Nc; j += 256) {
        float dx = xi0 - Xb[j*3+0];
        float dy = xi1 - Xb[j*3+1];
        float dz = xi2 - Xb[j*3+2];
        float d = sqrtf(dx*dx + dy*dy + dz*dz + 1e-6f);
        float D = mi * mb[j] * d;
        sD[j] = D;
        lmax = fmaxf(lmax, D);
    }
    #pragma unroll
    for (int o = 16; o > 0; o >>= 1) lmax = fmaxf(lmax, __shfl_xor_sync(0xffffffffu, lmax, o));
    if (lane == 0) red8[warp] = lmax;
    __syncthreads();
    if (tid == 0) {
        float m = red8[0];
        #pragma unroll
        for (int w = 1; w < 8; w++) m = fmaxf(m, red8[w]);
        s_rowmax = m;
    }
    __syncthreads();
    float rowmax = s_rowmax;
    for (int j = tid; j < Nc; j += 256) {
        float m2 = mi * mb[j];
        sD[j] = sD[j] + (1.f - m2) * rowmax;
    }
    __syncthreads();

    int s0 = warp * SEG;
    int s1 = min(Nc, s0 + SEG);
    {
        float v = 3.4e38f; int vi = 0x7fffffff;
        for (int j = s0 + lane; j < s1; j += 32) {
            float x = sD[j];
            if (x < v) { v = x; vi = j; }
        }
        #pragma unroll
        for (int o = 16; o > 0; o >>= 1) {
            float ov = __shfl_xor_sync(0xffffffffu, v, o);
            int   oi = __shfl_xor_sync(0xffffffffu, vi, o);
            if (ov < v || (ov == v && oi < vi)) { v = ov; vi = oi; }
        }
        if (lane == 0) { wmin[warp] = v; widx[warp] = vi; }
    }
    __syncthreads();

    for (int sel = 0; sel < Kc; sel++) {
        if (warp == 0) {
            float v = (lane < 8) ? wmin[lane] : 3.4e38f;
            int  vi = (lane < 8) ? widx[lane] : 0x7fffffff;
            #pragma unroll
            for (int o = 4; o > 0; o >>= 1) {
                float ov = __shfl_xor_sync(0xffffffffu, v, o);
                int   oi = __shfl_xor_sync(0xffffffffu, vi, o);
                if (ov < v || (ov == v && oi < vi)) { v = ov; vi = oi; }
            }
            if (lane == 0) {
                Eidx[(size_t)row*Kc + sel] = vi;
                sSel[sel]  = vi;
                sSelD[sel] = v;
                sD[vi] = 3.4e38f;
                s_win = vi / SEG;
            }
        }
        __syncthreads();
        if (warp == s_win) {
            float v = 3.4e38f; int vi = 0x7fffffff;
            for (int j = s0 + lane; j < s1; j += 32) {
                float x = sD[j];
                if (x < v) { v = x; vi = j; }
            }
            #pragma unroll
            for (int o = 16; o > 0; o >>= 1) {
                float ov = __shfl_xor_sync(0xffffffffu, v, o);
                int   oi = __shfl_xor_sync(0xffffffffu, vi, o);
                if (ov < v || (ov == v && oi < vi)) { v = ov; vi = oi; }
            }
            if (lane == 0) { wmin[warp] = v; widx[warp] = vi; }
        }
        __syncthreads();
    }

    // ---- Phase 2: edge features for this row's 30 edges ----
    int c = lane;
    for (int k = warp; k < Kc; k += 8) {
        int jsel  = sSel[k];
        float dnb = sSelD[k];
        float f;
        if (c < 16) {
            int mdx = c & 7;
            float freq = __expf((float)(2*mdx) * (-9.210340371976184f / 16.f));
            float d_rel = (float)(jsel - i);
            float ang = d_rel * freq;
            f = (c < 8) ? __cosf(ang) : __sinf(ang);
        } else {
            int r = c - 16;
            float mu_ = 20.f * (float)r / 15.f;
            float tt = (dnb - mu_) * (1.f / 1.25f);
            f = __expf(-tt * tt);
        }
        float mu = wred(f * mlane);
        float gf = 0.f;
        #pragma unroll
        for (int j = 0; j < 32; j++) {
            float fj = __shfl_sync(0xffffffffu, f, j);
            gf += Greg[j] * fj;
        }
        float ss = wred(f * gf);
        float var = ss * (1.f/128.f) - mu * mu;
        float inv = rsqrtf(var + 1e-6f);
        fs[((size_t)row*Kc + k)*32 + c] = f * inv;
        if (c == 0) ms[(size_t)row*Kc + k] = mu * inv;
    }
}

// ---------------- precompute 1 ----------------
__global__ void pre1_kernel(const float* __restrict__ W_edge, const float* __restrict__ W_e,
                            const float* __restrict__ lng, const float* __restrict__ lnb,
                            const float* __restrict__ b_e)
{
    int tid = threadIdx.x;
    if (blockIdx.x == 0) {
        if (tid < 128) {
            float s = 0.f, bp = 0.f;
            for (int c = 0; c < 128; c++) {
                float w = W_e[(size_t)c*128 + tid];
                s  += lng[c] * w;
                bp += lnb[c] * w;
            }
            g_s[tid] = s;
            g_bp[tid] = bp + b_e[tid];
        }
    } else if (blockIdx.x == 1) {
        if (tid < 32) {
            float acc = 0.f;
            for (int c = 0; c < 128; c++) acc += W_edge[tid*128 + c];
            g_m[tid] = acc * (1.f/128.f);
        }
        for (int t = tid; t < 1024; t += 256) {
            int i = t >> 5, j = t & 31;
            float acc = 0.f;
            for (int c = 0; c < 128; c++) acc += W_edge[i*128+c] * W_edge[j*128+c];
            g_G[t] = acc;
        }
    } else {
        for (int t = tid; t < 4096; t += 256) {
            int i = t >> 7, d = t & 127;
            float acc = 0.f;
            for (int c = 0; c < 128; c++)
                acc += W_edge[i*128+c] * lng[c] * W_e[(size_t)c*128 + d];
            g_Wcomb[t] = acc;
        }
    }
}

// ---------------- precompute 2 ----------------
__global__ void pre2_kernel(const float* __restrict__ Wk, const float* __restrict__ Wv)
{
    int l = blockIdx.x;
    int tid = threadIdx.x;
    const float* Wk_l = Wk + (size_t)l * 256 * 128;
    const float* Wv_l = Wv + (size_t)l * 256 * 128;
    for (int t = tid; t < 4096; t += 256) {
        int h = t >> 10, r = t & 1023, j = r >> 5, i = r & 31;
        float acc = 0.f;
        for (int c = 0; c < 128; c++)
            acc += g_Wcomb[i*128+c] * Wk_l[(size_t)c*128 + h*32 + j];
        g_At[l*4096 + h*1024 + j*32 + i] = acc;
    }
    for (int t = tid; t < 4096; t += 256) {
        int i = t >> 7, d = t & 127;
        float acc = 0.f;
        for (int c = 0; c < 128; c++)
            acc += g_Wcomb[i*128+c] * Wv_l[(size_t)c*128 + d];
        g_Wcv[l*4096 + t] = acc;
    }
    if (tid < 128) {
        float sv = 0.f, bv = 0.f, sv2 = 0.f, bv2 = 0.f;
        for (int c = 0; c < 128; c++) {
            float wk = Wk_l[(size_t)c*128 + tid];
            float wv = Wv_l[(size_t)c*128 + tid];
            sv  += g_s[c]  * wk;
            bv  += g_bp[c] * wk;
            sv2 += g_s[c]  * wv;
            bv2 += g_bp[c] * wv;
        }
        g_sv [l*128 + tid] = sv;
        g_bv [l*128 + tid] = bv;
        g_sv2[l*128 + tid] = sv2;
        g_bv2[l*128 + tid] = bv2;
    }
}

// ---------------- fused neighbor attention ----------------
__global__ void __launch_bounds__(128)
attn6_kernel(const float* __restrict__ Q, const float* __restrict__ Kn, const float* __restrict__ Vn,
             const float* __restrict__ fs, const float* __restrict__ ms,
             const int* __restrict__ Eidx, const float* __restrict__ mask,
             int l, float* __restrict__ out)
{
    __shared__ __align__(16) float sq[128];
    __shared__ float sfs[Kc*33];
    __shared__ float slg[4][32];
    __shared__ float sQe2[4][32];
    __shared__ float sa[4][32];
    __shared__ float sfa[4][32];
    __shared__ float sms_[Kc], smk[Kc];
    __shared__ int   sidx[Kc];
    __shared__ float sma[4], ssa[4];
    __shared__ __align__(16) float svp[4][128];

    int n = blockIdx.x;
    int tid = threadIdx.x;
    int h = tid >> 5, lane = tid & 31;
    int b = n / Nc;

    if (tid < Kc) {
        int j = Eidx[(size_t)n*Kc + tid];
        sidx[tid] = b * Nc + j;
        smk[tid]  = mask[(size_t)b*Nc + j];
        sms_[tid] = ms[(size_t)n*Kc + tid];
    }
    sq[tid] = Q[(size_t)n*128 + tid];
    for (int t = tid; t < Kc*32; t += 128) {
        int k = t >> 5, c = t & 31;
        sfs[k*33 + c] = fs[((size_t)n*Kc + k)*32 + c];
    }
    __syncthreads();

    float qh = sq[h*32 + lane];
    float sqv = wred(qh * g_sv[l*128 + h*32 + lane]);
    float bqv = wred(qh * g_bv[l*128 + h*32 + lane]);
    const float* Ath = g_At + l*4096 + h*1024;
    float qe2 = 0.f;
    #pragma unroll
    for (int j = 0; j < 32; j++) {
        float qj = __shfl_sync(0xffffffffu, qh, j);
        qe2 += Ath[j*32 + lane] * qj;
    }
    sQe2[h][lane] = qe2;

    float4 q4 = *(const float4*)(sq + lane*4);
    #pragma unroll
    for (int j = 0; j < 8; j++) {
        int k = h + 4*j;
        if (k < Kc) {
            const float4 kv = *(const float4*)(Kn + (size_t)sidx[k]*128 + lane*4);
            float p = q4.x*kv.x + q4.y*kv.y + q4.z*kv.z + q4.w*kv.w;
            p += __shfl_xor_sync(0xffffffffu, p, 1);
            p += __shfl_xor_sync(0xffffffffu, p, 2);
            p += __shfl_xor_sync(0xffffffffu, p, 4);
            if ((lane & 7) == 0) slg[lane >> 3][k] = p;
        }
    }
    __syncthreads();

    float mi = mask[n];
    float a = 0.f;
    {
        float mk = 0.f;
        float ex = 0.f;
        float x = -3.4028235e38f;
        if (lane < Kc) {
            mk = mi * smk[lane];
            float acc = bqv - sms_[lane] * sqv + slg[h][lane];
            #pragma unroll
            for (int i = 0; i < 32; i++)
                acc += sfs[lane*33 + i] * sQe2[h][i];
            acc *= 0.17677669529663687f;
            x = (mk > 0.f) ? acc : -3.4028235e38f;
        }
        float mx = x;
        #pragma unroll
        for (int o = 16; o > 0; o >>= 1) mx = fmaxf(mx, __shfl_xor_sync(0xffffffffu, mx, o));
        if (lane < Kc && mk > 0.f) ex = __expf(x - mx);
        float sm = wred(ex);
        a = (lane < Kc) ? (ex / sm) * mk : 0.f;
        sa[h][lane] = a;
    }
    float sa_tot = wred(a);
    float ma_tot = wred((lane < Kc) ? a * sms_[lane] : 0.f);
    if (lane == 0) { ssa[h] = sa_tot; sma[h] = ma_tot; }
    __syncwarp();

    float fa = 0.f;
    #pragma unroll 6
    for (int k = 0; k < Kc; k++)
        fa += sa[h][k] * sfs[k*33 + lane];
    sfa[h][lane] = fa;
    __syncthreads();

    {
        float4 vp = make_float4(0.f, 0.f, 0.f, 0.f);
        int hh = lane >> 3;
        #pragma unroll
        for (int j = 0; j < 8; j++) {
            int k = h + 4*j;
            if (k < Kc) {
                float aw = sa[hh][k];
                const float4 vv = *(const float4*)(Vn + (size_t)sidx[k]*128 + lane*4);
                vp.x += aw * vv.x; vp.y += aw * vv.y;
                vp.z += aw * vv.z; vp.w += aw * vv.w;
            }
        }
        *(float4*)(&svp[h][lane*4]) = vp;
    }
    __syncthreads();
    float vacc = svp[0][tid] + svp[1][tid] + svp[2][tid] + svp[3][tid];

    const float* Wcv_l = g_Wcv + l*4096;
    float ed = 0.f;
    #pragma unroll 8
    for (int i = 0; i < 32; i++)
        ed += sfa[h][i] * Wcv_l[i*128 + tid];
    out[(size_t)n*128 + tid] = vacc + ed - sma[h] * g_sv2[l*128 + tid] + ssa[h] * g_bv2[l*128 + tid];
}

// ---------------- final projection ----------------
__global__ void out_kernel(const float* __restrict__ hV, const float* __restrict__ Wout,
                           const float* __restrict__ bout, float* __restrict__ out)
{
    int node = blockIdx.x * 4 + (threadIdx.x >> 5);
    int lane = threadIdx.x & 31;
    if (node >= BNc) return;
    float acc = 0.f;
    #pragma unroll
    for (int m = 0; m < 4; m++)
        acc += hV[(size_t)node * 128 + lane + m * 32] * Wout[lane + m * 32];
    #pragma unroll
    for (int o = 16; o > 0; o >>= 1) acc += __shfl_xor_sync(0xffffffffu, acc, o);
    if (lane == 0) out[node] = acc + bout[0];
}

// ---------------- host launch ----------------
static void* symaddr(const void* sym) { void* p = nullptr; cudaGetSymbolAddress(&p, sym); return p; }

extern "C" void kernel_launch(void* const* d_in, const int* in_sizes, int n_in,
                              void* d_out, int out_size)
{
    const float* X      = (const float*)d_in[0];
    const float* V      = (const float*)d_in[1];
    const float* mask   = (const float*)d_in[2];
    const float* W_v    = (const float*)d_in[3];
    const float* b_v    = (const float*)d_in[4];
    const float* W_e    = (const float*)d_in[5];
    const float* b_e    = (const float*)d_in[6];
    const float* W_edge = (const float*)d_in[7];
    const float* ln_e_g = (const float*)d_in[8];
    const float* ln_e_b = (const float*)d_in[9];
    const float* Wq     = (const float*)d_in[10];
    const float* Wk     = (const float*)d_in[11];
    const float* Wv_a   = (const float*)d_in[12];
    const float* Wo     = (const float*)d_in[13];
    const float* ln1_g  = (const float*)d_in[14];
    const float* ln1_b  = (const float*)d_in[15];
    const float* ln2_g  = (const float*)d_in[16];
    const float* ln2_b  = (const float*)d_in[17];
    const float* W_ff1  = (const float*)d_in[18];
    const float* b_ff1  = (const float*)d_in[19];
    const float* W_ff2  = (const float*)d_in[20];
    const float* b_ff2  = (const float*)d_in[21];
    const float* W_out  = (const float*)d_in[22];
    const float* b_out  = (const float*)d_in[23];
    float* out = (float*)d_out;

    int*      pEidx = (int*)     symaddr(g_Eidx);
    float*    pFs   = (float*)   symaddr(g_fs);
    float*    pMs   = (float*)   symaddr(g_ms);
    float*    phVa  = (float*)   symaddr(g_hVa);
    float*    phVb  = (float*)   symaddr(g_hVb);
    float*    phVm  = (float*)   symaddr(g_hVm);
    float*    pQ    = (float*)   symaddr(g_Q);
    float*    pKn   = (float*)   symaddr(g_Kn);
    float*    pVn   = (float*)   symaddr(g_Vn);
    float*    pAtt  = (float*)   symaddr(g_att);
    float*    pFF   = (float*)   symaddr(g_ff);
    uint32_t* pWhi  = (uint32_t*)symaddr(g_Whi);
    uint32_t* pWlo  = (uint32_t*)symaddr(g_Wlo);

    const int gN64 = (BNc + 63) / 64;    // 94

    // pre1 must precede topk_edge (g_G / g_m dependency)
    pre1_kernel<<<3, 256>>>(W_edge, W_e, ln_e_g, ln_e_b, b_e);
    pre2_kernel<<<Lc, 256>>>(Wk, Wv_a);
    split_all_kernel<<<(ARENA_N + 255)/256, 256>>>(W_v, Wq, Wk, Wv_a, Wo, W_ff1, W_ff2);
    topk_edge_kernel<<<BNc, 256>>>(X, mask, pEidx, pFs, pMs);
    // hV init: 4-way split-K (K=1024 -> 4x256) into pQ/pKn/pVn/pAtt, then sum+bias
    tf32_gemm_splitk4<<<dim3(4, gN64), 256>>>(V, pWhi + OFF_WV, pWlo + OFF_WV,
                                              pQ, pKn, pVn, pAtt, BNc, 1024);
    sum4_bias_kernel<<<(BNc*128 + 255)/256, 256>>>(pQ, pKn, pVn, pAtt, b_v, phVa);

    float* cur = phVa;
    float* nxt = phVb;
    for (int l = 0; l < Lc; l++) {
        int lb = LOFF(l);
        tf32_gemm_qkv<<<dim3(3, gN64), 256>>>(cur, lb + LOFF_WQ, lb + LOFF_WK, lb + LOFF_WVB,
                                              pQ, pKn, pVn, BNc);
        attn6_kernel<<<BNc, 128>>>(pQ, pKn, pVn, pFs, pMs, pEidx, mask, l, pAtt);
        // Wo: 2-way split-K (K=128 -> 2x64) into pQ/pKn (dead), then sum+res+LN1
        tf32_gemm_splitk<<<dim3(2, gN64), 256>>>(pAtt, pWhi + lb + LOFF_WO, pWlo + lb + LOFF_WO,
                                                 pQ, pKn, BNc, 128);
        sum2_ln_kernel<0,0><<<BNc, 128>>>(pQ, pKn, nullptr, cur,
                                          ln1_g + l*128, ln1_b + l*128, nullptr, phVm);
        tf32_gemm<1,1><<<dim3(4, gN64), 256>>>(phVm, pWhi + lb + LOFF_FF1, pWlo + lb + LOFF_FF1,
                                               b_ff1 + l*512, pFF, BNc, 512, 128);
        // ff2: 2-way split-K (K=512 -> 2x256) into pQ/pKn, then sum+bias+res+LN2+mask
        tf32_gemm_splitk<<<dim3(2, gN64), 256>>>(pFF, pWhi + lb + LOFF_FF2, pWlo + lb + LOFF_FF2,
                                                 pQ, pKn, BNc, 512);
        sum2_ln_kernel<1,1><<<BNc, 128>>>(pQ, pKn, b_ff2 + l*128, phVm,
                                          ln2_g + l*128, ln2_b + l*128, mask, nxt);
        float* t = cur; cur = nxt; nxt = t;
    }
    out_kernel<<<(BNc + 3) / 4, 128>>>(cur, W_out, b_out, out);
}

// round 17
// speedup vs baseline: 1.0479x; 1.0479x over previous
#include <cuda_runtime.h>
#include <math.h>
#include <stdint.h>

// ---------------- problem constants ----------------
#define Bc 4
#define Nc 1500
#define Kc 30
#define Lc 4
#define BNc (Bc*Nc)          // 6000
#define ECNT (BNc*Kc)        // 180000
#define SEG 188              // 8*188 >= 1500

// weight arena layout (floats)
#define OFF_WV 0
#define LAYER_FLOATS 196608
#define ARENA_N (131072 + Lc*LAYER_FLOATS)   // 917504
#define LOFF(l) (131072 + (l)*LAYER_FLOATS)
#define LOFF_WQ  0
#define LOFF_WK  16384
#define LOFF_WVB 32768
#define LOFF_WO  49152
#define LOFF_FF1 65536
#define LOFF_FF2 131072

// ---------------- device scratch ----------------
__device__ int   g_Eidx[ECNT];
__device__ float g_Dnb[ECNT];
__device__ float g_fs[(size_t)ECNT*32];
__device__ float g_ms[ECNT];
__device__ float g_hVa[(size_t)BNc*128];
__device__ float g_hVb[(size_t)BNc*128];
__device__ float g_hVm[(size_t)BNc*128];
__device__ float g_Q[(size_t)BNc*128];
__device__ float g_Kn[(size_t)BNc*128];
__device__ float g_Vn[(size_t)BNc*128];
__device__ float g_att[(size_t)BNc*128];
__device__ float g_ff[(size_t)BNc*512];
__device__ uint32_t g_Whi[ARENA_N];
__device__ uint32_t g_Wlo[ARENA_N];
// precomputed constants
__device__ float g_Wcomb[32*128];
__device__ float g_G[32*32];
__device__ float g_m[32];
__device__ float g_s[128];
__device__ float g_bp[128];
__device__ float g_At[Lc*4*32*32];
__device__ float g_sv[Lc*128];
__device__ float g_bv[Lc*128];
__device__ float g_Wcv[Lc*32*128];
__device__ float g_sv2[Lc*128];
__device__ float g_bv2[Lc*128];

__device__ __forceinline__ float wred(float v) {
    #pragma unroll
    for (int o = 16; o > 0; o >>= 1) v += __shfl_xor_sync(0xffffffffu, v, o);
    return v;
}

__device__ __forceinline__ uint32_t f2tf(float x) {
    uint32_t r; asm("cvt.rna.tf32.f32 %0, %1;" : "=r"(r) : "f"(x)); return r;
}
__device__ __forceinline__ void f2tf2(float x, uint32_t& hi, uint32_t& lo) {
    hi = f2tf(x);
    lo = f2tf(x - __uint_as_float(hi));
}

__device__ __forceinline__ void mma8(float* c, const uint32_t* a, const uint32_t* b) {
    asm volatile("mma.sync.aligned.m16n8k8.row.col.f32.tf32.tf32.f32 "
        "{%0,%1,%2,%3}, {%4,%5,%6,%7}, {%8,%9}, {%0,%1,%2,%3};"
        : "+f"(c[0]), "+f"(c[1]), "+f"(c[2]), "+f"(c[3])
        : "r"(a[0]), "r"(a[1]), "r"(a[2]), "r"(a[3]), "r"(b[0]), "r"(b[1]));
}

#define SMEM_LOOP_BYTES 25600

// ---------------- weight split ----------------
__global__ void split_all_kernel(const float* __restrict__ W_v, const float* __restrict__ Wq,
                                 const float* __restrict__ Wk, const float* __restrict__ Wv_a,
                                 const float* __restrict__ Wo, const float* __restrict__ W_ff1,
                                 const float* __restrict__ W_ff2)
{
    int idx = blockIdx.x * 256 + threadIdx.x;
    if (idx >= ARENA_N) return;
    float v;
    if (idx < 131072) {
        v = W_v[idx];
    } else {
        int r = idx - 131072;
        int l = r / LAYER_FLOATS;
        int q = r - l * LAYER_FLOATS;
        if      (q < LOFF_WK)  v = Wq  [(size_t)l*16384 + q];
        else if (q < LOFF_WVB) v = Wk  [(size_t)l*32768 + 16384 + (q - LOFF_WK)];
        else if (q < LOFF_WO)  v = Wv_a[(size_t)l*32768 + 16384 + (q - LOFF_WVB)];
        else if (q < LOFF_FF1) v = Wo  [(size_t)l*16384 + (q - LOFF_WO)];
        else if (q < LOFF_FF2) v = W_ff1[(size_t)l*65536 + (q - LOFF_FF1)];
        else                   v = W_ff2[(size_t)l*65536 + (q - LOFF_FF2)];
    }
    uint32_t hi, lo;
    f2tf2(v, hi, lo);
    g_Whi[idx] = hi;
    g_Wlo[idx] = lo;
}

// ---------------- 3xTF32 mainloop, register-prefetched, 64x128 tile, 256 threads ----------------
__device__ __forceinline__ void tf32_loop3_pf(const float* __restrict__ A,
    const uint32_t* __restrict__ BHi, const uint32_t* __restrict__ BLo,
    int M, int Nn, int Kk, int Astride, int rowbase, int colbase, char* buf, float acc[2][4][4])
{
    uint32_t (*AsH)[17]  = reinterpret_cast<uint32_t(*)[17]>(buf);
    uint32_t (*AsL)[17]  = reinterpret_cast<uint32_t(*)[17]>(buf + 4352);
    uint32_t (*BsH)[132] = reinterpret_cast<uint32_t(*)[132]>(buf + 8704);
    uint32_t (*BsL)[132] = reinterpret_cast<uint32_t(*)[132]>(buf + 17152);

    int tid = threadIdx.x;
    int warp = tid >> 5, lane = tid & 31;
    int g = lane >> 2, t = lane & 3;
    int warpRow = warp >> 2, warpCol = warp & 3;
    int ar = tid >> 2;
    int ac = (tid & 3) * 4;
    int br = tid >> 5;
    int bc = (tid & 31) * 4;
    bool aval = (rowbase + ar) < M;
    const float* Arow = A + (size_t)(rowbase + ar) * Astride + ac;

    float4 av = aval ? *(const float4*)(Arow) : make_float4(0.f,0.f,0.f,0.f);
    uint4 bh0 = *(const uint4*)(BHi + (size_t)br * Nn + colbase + bc);
    uint4 bl0 = *(const uint4*)(BLo + (size_t)br * Nn + colbase + bc);
    uint4 bh1 = *(const uint4*)(BHi + (size_t)(br + 8) * Nn + colbase + bc);
    uint4 bl1 = *(const uint4*)(BLo + (size_t)(br + 8) * Nn + colbase + bc);
    f2tf2(av.x, AsH[ar][ac+0], AsL[ar][ac+0]);
    f2tf2(av.y, AsH[ar][ac+1], AsL[ar][ac+1]);
    f2tf2(av.z, AsH[ar][ac+2], AsL[ar][ac+2]);
    f2tf2(av.w, AsH[ar][ac+3], AsL[ar][ac+3]);
    *(uint4*)(&BsH[br][bc])     = bh0;
    *(uint4*)(&BsL[br][bc])     = bl0;
    *(uint4*)(&BsH[br + 8][bc]) = bh1;
    *(uint4*)(&BsL[br + 8][bc]) = bl1;
    __syncthreads();

    for (int k0 = 16; ; k0 += 16) {
        bool more = (k0 < Kk);
        if (more) {
            av  = aval ? *(const float4*)(Arow + k0) : make_float4(0.f,0.f,0.f,0.f);
            bh0 = *(const uint4*)(BHi + (size_t)(k0 + br) * Nn + colbase + bc);
            bl0 = *(const uint4*)(BLo + (size_t)(k0 + br) * Nn + colbase + bc);
            bh1 = *(const uint4*)(BHi + (size_t)(k0 + br + 8) * Nn + colbase + bc);
            bl1 = *(const uint4*)(BLo + (size_t)(k0 + br + 8) * Nn + colbase + bc);
        }
        #pragma unroll
        for (int kk = 0; kk < 2; kk++) {
            uint32_t aH[2][4], aL[2][4], bH[4][2], bL[4][2];
            #pragma unroll
            for (int mi = 0; mi < 2; mi++) {
                int rb = warpRow * 32 + mi * 16;
                aH[mi][0] = AsH[rb + g    ][kk*8 + t];
                aH[mi][1] = AsH[rb + g + 8][kk*8 + t];
                aH[mi][2] = AsH[rb + g    ][kk*8 + t + 4];
                aH[mi][3] = AsH[rb + g + 8][kk*8 + t + 4];
                aL[mi][0] = AsL[rb + g    ][kk*8 + t];
                aL[mi][1] = AsL[rb + g + 8][kk*8 + t];
                aL[mi][2] = AsL[rb + g    ][kk*8 + t + 4];
                aL[mi][3] = AsL[rb + g + 8][kk*8 + t + 4];
            }
            #pragma unroll
            for (int ni = 0; ni < 4; ni++) {
                int cb = warpCol * 32 + ni * 8 + g;
                bH[ni][0] = BsH[kk*8 + t    ][cb];
                bH[ni][1] = BsH[kk*8 + t + 4][cb];
                bL[ni][0] = BsL[kk*8 + t    ][cb];
                bL[ni][1] = BsL[kk*8 + t + 4][cb];
            }
            #pragma unroll
            for (int mi = 0; mi < 2; mi++)
                #pragma unroll
                for (int ni = 0; ni < 4; ni++) {
                    mma8(acc[mi][ni], aL[mi], bH[ni]);
                    mma8(acc[mi][ni], aH[mi], bL[ni]);
                    mma8(acc[mi][ni], aH[mi], bH[ni]);
                }
        }
        if (!more) break;
        __syncthreads();
        f2tf2(av.x, AsH[ar][ac+0], AsL[ar][ac+0]);
        f2tf2(av.y, AsH[ar][ac+1], AsL[ar][ac+1]);
        f2tf2(av.z, AsH[ar][ac+2], AsL[ar][ac+2]);
        f2tf2(av.w, AsH[ar][ac+3], AsL[ar][ac+3]);
        *(uint4*)(&BsH[br][bc])     = bh0;
        *(uint4*)(&BsL[br][bc])     = bl0;
        *(uint4*)(&BsH[br + 8][bc]) = bh1;
        *(uint4*)(&BsL[br + 8][bc]) = bl1;
        __syncthreads();
    }
    __syncthreads();
}

// ---------------- epilogue helper ----------------
__device__ __forceinline__ void gemm_store(float acc[2][4][4], const float* bias, float* C,
                                           int M, int Nn, int rowbase, int colbase,
                                           int BIAS, int RELU)
{
    int warp = threadIdx.x >> 5, lane = threadIdx.x & 31;
    int g = lane >> 2, t = lane & 3;
    int warpRow = warp >> 2, warpCol = warp & 3;
    #pragma unroll
    for (int mi = 0; mi < 2; mi++) {
        #pragma unroll
        for (int ni = 0; ni < 4; ni++) {
            int col = colbase + warpCol * 32 + ni * 8 + 2 * t;
            float b0 = BIAS ? bias[col]   : 0.f;
            float b1 = BIAS ? bias[col+1] : 0.f;
            int r0 = rowbase + warpRow * 32 + mi * 16 + g;
            if (r0 < M) {
                float2 o; o.x = acc[mi][ni][0] + b0; o.y = acc[mi][ni][1] + b1;
                if (RELU) { o.x = fmaxf(o.x, 0.f); o.y = fmaxf(o.y, 0.f); }
                *(float2*)(C + (size_t)r0 * Nn + col) = o;
            }
            int r1 = r0 + 8;
            if (r1 < M) {
                float2 o; o.x = acc[mi][ni][2] + b0; o.y = acc[mi][ni][3] + b1;
                if (RELU) { o.x = fmaxf(o.x, 0.f); o.y = fmaxf(o.y, 0.f); }
                *(float2*)(C + (size_t)r1 * Nn + col) = o;
            }
        }
    }
}

// ---------------- tf32x3 GEMM + bias/relu (256 threads) ----------------
template<int BIAS, int RELU>
__global__ void __launch_bounds__(256)
tf32_gemm(const float* __restrict__ A, const uint32_t* __restrict__ BHi, const uint32_t* __restrict__ BLo,
          const float* __restrict__ bias, float* __restrict__ C,
          int M, int Nn, int Kk)
{
    __shared__ __align__(16) char buf[SMEM_LOOP_BYTES];
    float acc[2][4][4];
    #pragma unroll
    for (int mi = 0; mi < 2; mi++)
        #pragma unroll
        for (int ni = 0; ni < 4; ni++)
            #pragma unroll
            for (int q = 0; q < 4; q++) acc[mi][ni][q] = 0.f;

    int rowbase = blockIdx.y * 64, colbase = blockIdx.x * 128;
    tf32_loop3_pf(A, BHi, BLo, M, Nn, Kk, Kk, rowbase, colbase, buf, acc);
    gemm_store(acc, bias, C, M, Nn, rowbase, colbase, BIAS, RELU);
}

// ---------------- 2-way split-K GEMM ----------------
__global__ void __launch_bounds__(256)
tf32_gemm_splitk(const float* __restrict__ A, const uint32_t* __restrict__ BHi, const uint32_t* __restrict__ BLo,
                 float* __restrict__ C0, float* __restrict__ C1, int M, int Kfull)
{
    __shared__ __align__(16) char buf[SMEM_LOOP_BYTES];
    float acc[2][4][4];
    #pragma unroll
    for (int mi = 0; mi < 2; mi++)
        #pragma unroll
        for (int ni = 0; ni < 4; ni++)
            #pragma unroll
            for (int q = 0; q < 4; q++) acc[mi][ni][q] = 0.f;

    int half = Kfull >> 1;
    int koff = blockIdx.x * half;
    float* C = (blockIdx.x == 0) ? C0 : C1;
    int rowbase = blockIdx.y * 64;
    tf32_loop3_pf(A + koff, BHi + (size_t)koff * 128, BLo + (size_t)koff * 128,
                  M, 128, half, Kfull, rowbase, 0, buf, acc);
    gemm_store(acc, nullptr, C, M, 128, rowbase, 0, 0, 0);
}

// ---------------- 4-way split-K GEMM ----------------
__global__ void __launch_bounds__(256)
tf32_gemm_splitk4(const float* __restrict__ A, const uint32_t* __restrict__ BHi, const uint32_t* __restrict__ BLo,
                  float* __restrict__ C0, float* __restrict__ C1,
                  float* __restrict__ C2, float* __restrict__ C3, int M, int Kfull)
{
    __shared__ __align__(16) char buf[SMEM_LOOP_BYTES];
    float acc[2][4][4];
    #pragma unroll
    for (int mi = 0; mi < 2; mi++)
        #pragma unroll
        for (int ni = 0; ni < 4; ni++)
            #pragma unroll
            for (int q = 0; q < 4; q++) acc[mi][ni][q] = 0.f;

    int quarter = Kfull >> 2;
    int koff = blockIdx.x * quarter;
    float* C = (blockIdx.x == 0) ? C0 : (blockIdx.x == 1) ? C1 : (blockIdx.x == 2) ? C2 : C3;
    int rowbase = blockIdx.y * 64;
    tf32_loop3_pf(A + koff, BHi + (size_t)koff * 128, BLo + (size_t)koff * 128,
                  M, 128, quarter, Kfull, rowbase, 0, buf, acc);
    gemm_store(acc, nullptr, C, M, 128, rowbase, 0, 0, 0);
}

// ---------------- tf32x3 qkv GEMM ----------------
__global__ void __launch_bounds__(256)
tf32_gemm_qkv(const float* __restrict__ A, int off0, int off1, int off2,
              float* __restrict__ C0, float* __restrict__ C1, float* __restrict__ C2, int M)
{
    __shared__ __align__(16) char buf[SMEM_LOOP_BYTES];
    int off = (blockIdx.x == 0) ? off0 : (blockIdx.x == 1) ? off1 : off2;
    const uint32_t* BHi = g_Whi + off;
    const uint32_t* BLo = g_Wlo + off;
    float* C = (blockIdx.x == 0) ? C0 : (blockIdx.x == 1) ? C1 : C2;
    float acc[2][4][4];
    #pragma unroll
    for (int mi = 0; mi < 2; mi++)
        #pragma unroll
        for (int ni = 0; ni < 4; ni++)
            #pragma unroll
            for (int q = 0; q < 4; q++) acc[mi][ni][q] = 0.f;

    int rowbase = blockIdx.y * 64;
    tf32_loop3_pf(A, BHi, BLo, M, 128, 128, 128, rowbase, 0, buf, acc);
    gemm_store(acc, nullptr, C, M, 128, rowbase, 0, 0, 0);
}

// ---------------- split-K epilogue: out = p0+p1+p2+p3+bias ----------------
__global__ void sum4_bias_kernel(const float* __restrict__ p0, const float* __restrict__ p1,
                                 const float* __restrict__ p2, const float* __restrict__ p3,
                                 const float* __restrict__ bias, float* __restrict__ out)
{
    int t = blockIdx.x * 256 + threadIdx.x;
    if (t >= BNc * 128) return;
    out[t] = p0[t] + p1[t] + p2[t] + p3[t] + bias[t & 127];
}

// ---------------- split-K epilogue: out = (mask)*LN(p0+p1+(bias)+res) ----------------
template<int BIAS, int MASK>
__global__ void sum2_ln_kernel(const float* __restrict__ p0, const float* __restrict__ p1,
                               const float* __restrict__ bias, const float* __restrict__ res,
                               const float* __restrict__ gamma, const float* __restrict__ beta,
                               const float* __restrict__ mask, float* __restrict__ out)
{
    int row = blockIdx.x;
    int c = threadIdx.x;  // 128
    size_t idx = (size_t)row * 128 + c;
    float v = p0[idx] + p1[idx] + res[idx];
    if (BIAS) v += bias[c];
    float s = v, s2 = v * v;
    #pragma unroll
    for (int o = 16; o > 0; o >>= 1) {
        s  += __shfl_xor_sync(0xffffffffu, s,  o);
        s2 += __shfl_xor_sync(0xffffffffu, s2, o);
    }
    __shared__ float ws[4], ws2[4];
    int w = c >> 5;
    if ((c & 31) == 0) { ws[w] = s; ws2[w] = s2; }
    __syncthreads();
    s  = ws[0] + ws[1] + ws[2] + ws[3];
    s2 = ws2[0] + ws2[1] + ws2[2] + ws2[3];
    float mu = s * (1.f / 128.f);
    float var = s2 * (1.f / 128.f) - mu * mu;
    float y = gamma[c] * (v - mu) * rsqrtf(var + 1e-6f) + beta[c];
    if (MASK) y *= mask[row];
    out[idx] = y;
}

// ---------------- top-K: 8-warp build, single-warp selection loop ----------------
__global__ void __launch_bounds__(256)
topk_kernel(const float* __restrict__ X, const float* __restrict__ mask,
            int* __restrict__ Eidx, float* __restrict__ Dnb)
{
    __shared__ float sD[Nc];
    __shared__ float wmin[8];
    __shared__ int   widx[8];
    __shared__ float red8[8];
    __shared__ float s_rowmax;
    int row = blockIdx.x;
    int b = row / Nc;
    int i = row - b * Nc;
    int tid = threadIdx.x;
    int warp = tid >> 5, lane = tid & 31;
    const float* Xb = X + (size_t)b * Nc * 3;
    const float* mb = mask + (size_t)b * Nc;
    float xi0 = Xb[i*3+0], xi1 = Xb[i*3+1], xi2 = Xb[i*3+2];
    float mi = mb[i];
    float lmax = 0.f;
    for (int j = tid; j < Nc; j += 256) {
        float dx = xi0 - Xb[j*3+0];
        float dy = xi1 - Xb[j*3+1];
        float dz = xi2 - Xb[j*3+2];
        float d = sqrtf(dx*dx + dy*dy + dz*dz + 1e-6f);
        float D = mi * mb[j] * d;
        sD[j] = D;
        lmax = fmaxf(lmax, D);
    }
    #pragma unroll
    for (int o = 16; o > 0; o >>= 1) lmax = fmaxf(lmax, __shfl_xor_sync(0xffffffffu, lmax, o));
    if (lane == 0) red8[warp] = lmax;
    __syncthreads();
    if (tid == 0) {
        float m = red8[0];
        #pragma unroll
        for (int w = 1; w < 8; w++) m = fmaxf(m, red8[w]);
        s_rowmax = m;
    }
    __syncthreads();
    float rowmax = s_rowmax;
    for (int j = tid; j < Nc; j += 256) {
        float m2 = mi * mb[j];
        sD[j] = sD[j] + (1.f - m2) * rowmax;
    }
    __syncthreads();

    // per-warp segment minima (all 8 warps)
    {
        int s0 = warp * SEG;
        int s1 = min(Nc, s0 + SEG);
        float v = 3.4e38f; int vi = 0x7fffffff;
        for (int j = s0 + lane; j < s1; j += 32) {
            float x = sD[j];
            if (x < v) { v = x; vi = j; }
        }
        #pragma unroll
        for (int o = 16; o > 0; o >>= 1) {
            float ov = __shfl_xor_sync(0xffffffffu, v, o);
            int   oi = __shfl_xor_sync(0xffffffffu, vi, o);
            if (ov < v || (ov == v && oi < vi)) { v = ov; vi = oi; }
        }
        if (lane == 0) { wmin[warp] = v; widx[warp] = vi; }
    }
    __syncthreads();

    if (warp != 0) return;   // warps 1..7 done; warp 0 runs the selection alone

    // lane s (s<8) carries segment s's (min,idx) state in registers
    float v = (lane < 8) ? wmin[lane] : 3.4e38f;
    int  vi = (lane < 8) ? widx[lane] : 0x7fffffff;

    for (int sel = 0; sel < Kc; sel++) {
        // 8-lane lex-min butterfly (lanes 0..7 form a closed xor group)
        float bv = v; int bi = vi;
        #pragma unroll
        for (int o = 4; o > 0; o >>= 1) {
            float ov = __shfl_xor_sync(0xffffffffu, bv, o);
            int   oi = __shfl_xor_sync(0xffffffffu, bi, o);
            if (ov < bv || (ov == bv && oi < bi)) { bv = ov; bi = oi; }
        }
        float selv = __shfl_sync(0xffffffffu, bv, 0);
        int   seli = __shfl_sync(0xffffffffu, bi, 0);
        if (lane == 0) {
            Eidx[(size_t)row*Kc + sel] = seli;
            Dnb [(size_t)row*Kc + sel] = selv;
            sD[seli] = 3.4e38f;
        }
        __syncwarp();
        // rescan only the winning segment with the full warp
        int wseg = seli / SEG;
        int s0 = wseg * SEG;
        int s1 = min(Nc, s0 + SEG);
        float nv = 3.4e38f; int nvi = 0x7fffffff;
        for (int j = s0 + lane; j < s1; j += 32) {
            float x = sD[j];
            if (x < nv) { nv = x; nvi = j; }
        }
        #pragma unroll
        for (int o = 16; o > 0; o >>= 1) {
            float ov = __shfl_xor_sync(0xffffffffu, nv, o);
            int   oi = __shfl_xor_sync(0xffffffffu, nvi, o);
            if (ov < nv || (ov == nv && oi < nvi)) { nv = ov; nvi = oi; }
        }
        if (lane == wseg) { v = nv; vi = nvi; }
    }
}

// ---------------- precompute 1 ----------------
__global__ void pre1_kernel(const float* __restrict__ W_edge, const float* __restrict__ W_e,
                            const float* __restrict__ lng, const float* __restrict__ lnb,
                            const float* __restrict__ b_e)
{
    int tid = threadIdx.x;
    if (blockIdx.x == 0) {
        if (tid < 128) {
            float s = 0.f, bp = 0.f;
            for (int c = 0; c < 128; c++) {
                float w = W_e[(size_t)c*128 + tid];
                s  += lng[c] * w;
                bp += lnb[c] * w;
            }
            g_s[tid] = s;
            g_bp[tid] = bp + b_e[tid];
        }
    } else if (blockIdx.x == 1) {
        if (tid < 32) {
            float acc = 0.f;
            for (int c = 0; c < 128; c++) acc += W_edge[tid*128 + c];
            g_m[tid] = acc * (1.f/128.f);
        }
        for (int t = tid; t < 1024; t += 256) {
            int i = t >> 5, j = t & 31;
            float acc = 0.f;
            for (int c = 0; c < 128; c++) acc += W_edge[i*128+c] * W_edge[j*128+c];
            g_G[t] = acc;
        }
    } else {
        for (int t = tid; t < 4096; t += 256) {
            int i = t >> 7, d = t & 127;
            float acc = 0.f;
            for (int c = 0; c < 128; c++)
                acc += W_edge[i*128+c] * lng[c] * W_e[(size_t)c*128 + d];
            g_Wcomb[t] = acc;
        }
    }
}

// ---------------- precompute 2 ----------------
__global__ void pre2_kernel(const float* __restrict__ Wk, const float* __restrict__ Wv)
{
    int l = blockIdx.x;
    int tid = threadIdx.x;
    const float* Wk_l = Wk + (size_t)l * 256 * 128;
    const float* Wv_l = Wv + (size_t)l * 256 * 128;
    for (int t = tid; t < 4096; t += 256) {
        int h = t >> 10, r = t & 1023, j = r >> 5, i = r & 31;
        float acc = 0.f;
        for (int c = 0; c < 128; c++)
            acc += g_Wcomb[i*128+c] * Wk_l[(size_t)c*128 + h*32 + j];
        g_At[l*4096 + h*1024 + j*32 + i] = acc;
    }
    for (int t = tid; t < 4096; t += 256) {
        int i = t >> 7, d = t & 127;
        float acc = 0.f;
        for (int c = 0; c < 128; c++)
            acc += g_Wcomb[i*128+c] * Wv_l[(size_t)c*128 + d];
        g_Wcv[l*4096 + t] = acc;
    }
    if (tid < 128) {
        float sv = 0.f, bv = 0.f, sv2 = 0.f, bv2 = 0.f;
        for (int c = 0; c < 128; c++) {
            float wk = Wk_l[(size_t)c*128 + tid];
            float wv = Wv_l[(size_t)c*128 + tid];
            sv  += g_s[c]  * wk;
            bv  += g_bp[c] * wk;
            sv2 += g_s[c]  * wv;
            bv2 += g_bp[c] * wv;
        }
        g_sv [l*128 + tid] = sv;
        g_bv [l*128 + tid] = bv;
        g_sv2[l*128 + tid] = sv2;
        g_bv2[l*128 + tid] = bv2;
    }
}

// ---------------- fused edge features -> (feat/sigma, mu/sigma) ----------------
__global__ void __launch_bounds__(256)
edge_fs_kernel(const int* __restrict__ Eidx, const float* __restrict__ Dnb,
               float* __restrict__ fs, float* __restrict__ ms)
{
    __shared__ float sG[1024];
    __shared__ float sm[32];
    int tid = threadIdx.x;
    for (int t = tid; t < 1024; t += 256) sG[t] = g_G[t];
    if (tid < 32) sm[tid] = g_m[tid];
    __syncthreads();

    int e = blockIdx.x * 8 + (tid >> 5);
    int c = tid & 31;
    float f;
    if (c < 16) {
        int mdx = c & 7;
        float freq = __expf((float)(2*mdx) * (-9.210340371976184f / 16.f));
        int node = e / Kc;
        int i = node % Nc;
        float d_rel = (float)(Eidx[e] - i);
        float ang = d_rel * freq;
        f = (c < 8) ? __cosf(ang) : __sinf(ang);
    } else {
        int r = c - 16;
        float mu = 20.f * (float)r / 15.f;
        float tt = (Dnb[e] - mu) * (1.f / 1.25f);
        f = __expf(-tt * tt);
    }
    float mu = wred(f * sm[c]);
    float gf = 0.f;
    #pragma unroll
    for (int j = 0; j < 32; j++) {
        float fj = __shfl_sync(0xffffffffu, f, j);
        gf += sG[j*32 + c] * fj;
    }
    float ss = wred(f * gf);
    float var = ss * (1.f/128.f) - mu * mu;
    float inv = rsqrtf(var + 1e-6f);
    fs[(size_t)e*32 + c] = f * inv;
    if (c == 0) ms[e] = mu * inv;
}

// ---------------- fused neighbor attention ----------------
__global__ void __launch_bounds__(128)
attn6_kernel(const float* __restrict__ Q, const float* __restrict__ Kn, const float* __restrict__ Vn,
             const float* __restrict__ fs, const float* __restrict__ ms,
             const int* __restrict__ Eidx, const float* __restrict__ mask,
             int l, float* __restrict__ out)
{
    __shared__ __align__(16) float sq[128];
    __shared__ float sfs[Kc*33];
    __shared__ float slg[4][32];
    __shared__ float sQe2[4][32];
    __shared__ float sa[4][32];
    __shared__ float sfa[4][32];
    __shared__ float sms_[Kc], smk[Kc];
    __shared__ int   sidx[Kc];
    __shared__ float sma[4], ssa[4];
    __shared__ __align__(16) float svp[4][128];

    int n = blockIdx.x;
    int tid = threadIdx.x;
    int h = tid >> 5, lane = tid & 31;
    int b = n / Nc;

    if (tid < Kc) {
        int j = Eidx[(size_t)n*Kc + tid];
        sidx[tid] = b * Nc + j;
        smk[tid]  = mask[(size_t)b*Nc + j];
        sms_[tid] = ms[(size_t)n*Kc + tid];
    }
    sq[tid] = Q[(size_t)n*128 + tid];
    for (int t = tid; t < Kc*32; t += 128) {
        int k = t >> 5, c = t & 31;
        sfs[k*33 + c] = fs[((size_t)n*Kc + k)*32 + c];
    }
    __syncthreads();

    float qh = sq[h*32 + lane];
    float sqv = wred(qh * g_sv[l*128 + h*32 + lane]);
    float bqv = wred(qh * g_bv[l*128 + h*32 + lane]);
    const float* Ath = g_At + l*4096 + h*1024;
    float qe2 = 0.f;
    #pragma unroll
    for (int j = 0; j < 32; j++) {
        float qj = __shfl_sync(0xffffffffu, qh, j);
        qe2 += Ath[j*32 + lane] * qj;
    }
    sQe2[h][lane] = qe2;

    float4 q4 = *(const float4*)(sq + lane*4);
    #pragma unroll
    for (int j = 0; j < 8; j++) {
        int k = h + 4*j;
        if (k < Kc) {
            const float4 kv = *(const float4*)(Kn + (size_t)sidx[k]*128 + lane*4);
            float p = q4.x*kv.x + q4.y*kv.y + q4.z*kv.z + q4.w*kv.w;
            p += __shfl_xor_sync(0xffffffffu, p, 1);
            p += __shfl_xor_sync(0xffffffffu, p, 2);
            p += __shfl_xor_sync(0xffffffffu, p, 4);
            if ((lane & 7) == 0) slg[lane >> 3][k] = p;
        }
    }
    __syncthreads();

    float mi = mask[n];
    float a = 0.f;
    {
        float mk = 0.f;
        float ex = 0.f;
        float x = -3.4028235e38f;
        if (lane < Kc) {
            mk = mi * smk[lane];
            float acc = bqv - sms_[lane] * sqv + slg[h][lane];
            #pragma unroll
            for (int i = 0; i < 32; i++)
                acc += sfs[lane*33 + i] * sQe2[h][i];
            acc *= 0.17677669529663687f;
            x = (mk > 0.f) ? acc : -3.4028235e38f;
        }
        float mx = x;
        #pragma unroll
        for (int o = 16; o > 0; o >>= 1) mx = fmaxf(mx, __shfl_xor_sync(0xffffffffu, mx, o));
        if (lane < Kc && mk > 0.f) ex = __expf(x - mx);
        float sm = wred(ex);
        a = (lane < Kc) ? (ex / sm) * mk : 0.f;
        sa[h][lane] = a;
    }
    float sa_tot = wred(a);
    float ma_tot = wred((lane < Kc) ? a * sms_[lane] : 0.f);
    if (lane == 0) { ssa[h] = sa_tot; sma[h] = ma_tot; }
    __syncwarp();

    float fa = 0.f;
    #pragma unroll 6
    for (int k = 0; k < Kc; k++)
        fa += sa[h][k] * sfs[k*33 + lane];
    sfa[h][lane] = fa;
    __syncthreads();

    {
        float4 vp = make_float4(0.f, 0.f, 0.f, 0.f);
        int hh = lane >> 3;
        #pragma unroll
        for (int j = 0; j < 8; j++) {
            int k = h + 4*j;
            if (k < Kc) {
                float aw = sa[hh][k];
                const float4 vv = *(const float4*)(Vn + (size_t)sidx[k]*128 + lane*4);
                vp.x += aw * vv.x; vp.y += aw * vv.y;
                vp.z += aw * vv.z; vp.w += aw * vv.w;
            }
        }
        *(float4*)(&svp[h][lane*4]) = vp;
    }
    __syncthreads();
    float vacc = svp[0][tid] + svp[1][tid] + svp[2][tid] + svp[3][tid];

    const float* Wcv_l = g_Wcv + l*4096;
    float ed = 0.f;
    #pragma unroll 8
    for (int i = 0; i < 32; i++)
        ed += sfa[h][i] * Wcv_l[i*128 + tid];
    out[(size_t)n*128 + tid] = vacc + ed - sma[h] * g_sv2[l*128 + tid] + ssa[h] * g_bv2[l*128 + tid];
}

// ---------------- final projection ----------------
__global__ void out_kernel(const float* __restrict__ hV, const float* __restrict__ Wout,
                           const float* __restrict__ bout, float* __restrict__ out)
{
    int node = blockIdx.x * 4 + (threadIdx.x >> 5);
    int lane = threadIdx.x & 31;
    if (node >= BNc) return;
    float acc = 0.f;
    #pragma unroll
    for (int m = 0; m < 4; m++)
        acc += hV[(size_t)node * 128 + lane + m * 32] * Wout[lane + m * 32];
    #pragma unroll
    for (int o = 16; o > 0; o >>= 1) acc += __shfl_xor_sync(0xffffffffu, acc, o);
    if (lane == 0) out[node] = acc + bout[0];
}

// ---------------- host launch ----------------
static void* symaddr(const void* sym) { void* p = nullptr; cudaGetSymbolAddress(&p, sym); return p; }

extern "C" void kernel_launch(void* const* d_in, const int* in_sizes, int n_in,
                              void* d_out, int out_size)
{
    const float* X      = (const float*)d_in[0];
    const float* V      = (const float*)d_in[1];
    const float* mask   = (const float*)d_in[2];
    const float* W_v    = (const float*)d_in[3];
    const float* b_v    = (const float*)d_in[4];
    const float* W_e    = (const float*)d_in[5];
    const float* b_e    = (const float*)d_in[6];
    const float* W_edge = (const float*)d_in[7];
    const float* ln_e_g = (const float*)d_in[8];
    const float* ln_e_b = (const float*)d_in[9];
    const float* Wq     = (const float*)d_in[10];
    const float* Wk     = (const float*)d_in[11];
    const float* Wv_a   = (const float*)d_in[12];
    const float* Wo     = (const float*)d_in[13];
    const float* ln1_g  = (const float*)d_in[14];
    const float* ln1_b  = (const float*)d_in[15];
    const float* ln2_g  = (const float*)d_in[16];
    const float* ln2_b  = (const float*)d_in[17];
    const float* W_ff1  = (const float*)d_in[18];
    const float* b_ff1  = (const float*)d_in[19];
    const float* W_ff2  = (const float*)d_in[20];
    const float* b_ff2  = (const float*)d_in[21];
    const float* W_out  = (const float*)d_in[22];
    const float* b_out  = (const float*)d_in[23];
    float* out = (float*)d_out;

    int*      pEidx = (int*)     symaddr(g_Eidx);
    float*    pDnb  = (float*)   symaddr(g_Dnb);
    float*    pFs   = (float*)   symaddr(g_fs);
    float*    pMs   = (float*)   symaddr(g_ms);
    float*    phVa  = (float*)   symaddr(g_hVa);
    float*    phVb  = (float*)   symaddr(g_hVb);
    float*    phVm  = (float*)   symaddr(g_hVm);
    float*    pQ    = (float*)   symaddr(g_Q);
    float*    pKn   = (float*)   symaddr(g_Kn);
    float*    pVn   = (float*)   symaddr(g_Vn);
    float*    pAtt  = (float*)   symaddr(g_att);
    float*    pFF   = (float*)   symaddr(g_ff);
    uint32_t* pWhi  = (uint32_t*)symaddr(g_Whi);
    uint32_t* pWlo  = (uint32_t*)symaddr(g_Wlo);

    const int gN64 = (BNc + 63) / 64;    // 94

    topk_kernel<<<BNc, 256>>>(X, mask, pEidx, pDnb);
    pre1_kernel<<<3, 256>>>(W_edge, W_e, ln_e_g, ln_e_b, b_e);
    pre2_kernel<<<Lc, 256>>>(Wk, Wv_a);
    split_all_kernel<<<(ARENA_N + 255)/256, 256>>>(W_v, Wq, Wk, Wv_a, Wo, W_ff1, W_ff2);
    edge_fs_kernel<<<ECNT/8, 256>>>(pEidx, pDnb, pFs, pMs);
    // hV init: 4-way split-K (K=1024 -> 4x256) into pQ/pKn/pVn/pAtt, then sum+bias
    tf32_gemm_splitk4<<<dim3(4, gN64), 256>>>(V, pWhi + OFF_WV, pWlo + OFF_WV,
                                              pQ, pKn, pVn, pAtt, BNc, 1024);
    sum4_bias_kernel<<<(BNc*128 + 255)/256, 256>>>(pQ, pKn, pVn, pAtt, b_v, phVa);

    float* cur = phVa;
    float* nxt = phVb;
    for (int l = 0; l < Lc; l++) {
        int lb = LOFF(l);
        tf32_gemm_qkv<<<dim3(3, gN64), 256>>>(cur, lb + LOFF_WQ, lb + LOFF_WK, lb + LOFF_WVB,
                                              pQ, pKn, pVn, BNc);
        attn6_kernel<<<BNc, 128>>>(pQ, pKn, pVn, pFs, pMs, pEidx, mask, l, pAtt);
        // Wo: 2-way split-K (K=128 -> 2x64) into pQ/pKn (dead), then sum+res+LN1
        tf32_gemm_splitk<<<dim3(2, gN64), 256>>>(pAtt, pWhi + lb + LOFF_WO, pWlo + lb + LOFF_WO,
                                                 pQ, pKn, BNc, 128);
        sum2_ln_kernel<0,0><<<BNc, 128>>>(pQ, pKn, nullptr, cur,
                                          ln1_g + l*128, ln1_b + l*128, nullptr, phVm);
        tf32_gemm<1,1><<<dim3(4, gN64), 256>>>(phVm, pWhi + lb + LOFF_FF1, pWlo + lb + LOFF_FF1,
                                               b_ff1 + l*512, pFF, BNc, 512, 128);
        // ff2: 2-way split-K (K=512 -> 2x256) into pQ/pKn, then sum+bias+res+LN2+mask
        tf32_gemm_splitk<<<dim3(2, gN64), 256>>>(pFF, pWhi + lb + LOFF_FF2, pWlo + lb + LOFF_FF2,
                                                 pQ, pKn, BNc, 512);
        sum2_ln_kernel<1,1><<<BNc, 128>>>(pQ, pKn, b_ff2 + l*128, phVm,
                                          ln2_g + l*128, ln2_b + l*128, mask, nxt);
        float* t = cur; cur = nxt; nxt = t;
    }
    out_kernel<<<(BNc + 3) / 4, 128>>>(cur, W_out, b_out, out);
}